// round 17
// baseline (speedup 1.0000x reference)
#include <cuda_runtime.h>
#include <cuda_bf16.h>
#include <cstdint>
#include <math.h>

#define BATCH 2
#define LSEQ  2048
#define DM    512
#define NH    8
#define HD    64
#define DFF   2048
#define UTOP  409
#define NBH   (BATCH*NH)      // 16
#define NROWS (BATCH*LSEQ)    // 4096
#define TKCH  64              // topk chunks per (b,h)

// ================= scratch =================
__device__ __align__(16) float g_qb [NROWS*DM];
__device__ __align__(16) float g_kb [NROWS*DM];
__device__ __align__(16) float g_ctx[NBH*UTOP*HD];
__device__ __align__(16) float g_x1 [NROWS*DM];
__device__ __align__(16) float g_x2 [NROWS*DM];
__device__ __align__(16) int   g_ti [NBH*UTOP];
__device__ __align__(16) float g_kpart[NBH*TKCH*64];
__device__ __align__(16) uint32_t g_keys[NBH*LSEQ];

__device__ __align__(16) __nv_bfloat16 g_xnh[NROWS*DM],  g_xnl[NROWS*DM];
__device__ __align__(16) __nv_bfloat16 g_cfh[NROWS*DM],  g_cfl[NROWS*DM];
__device__ __align__(16) __nv_bfloat16 g_hidh[NROWS*DFF], g_hidl[NROWS*DFF];
__device__ __align__(16) __nv_bfloat16 g_qh[NROWS*DM],  g_ql[NROWS*DM];
__device__ __align__(16) __nv_bfloat16 g_kh[NROWS*DM],  g_kl[NROWS*DM];
__device__ __align__(16) __nv_bfloat16 g_vh[NROWS*DM],  g_vl[NROWS*DM];
__device__ __align__(16) __nv_bfloat16 g_wqkvh[3*DM*DM], g_wqkvl[3*DM*DM];
__device__ __align__(16) __nv_bfloat16 g_woh[DM*DM], g_wol[DM*DM];
__device__ __align__(16) __nv_bfloat16 g_cwqh[DM*DM], g_cwql[DM*DM];
__device__ __align__(16) __nv_bfloat16 g_cwkvh[2*DM*DM], g_cwkvl[2*DM*DM];
__device__ __align__(16) __nv_bfloat16 g_cwoh[DM*DM], g_cwol[DM*DM];
__device__ __align__(16) __nv_bfloat16 g_w1h[DM*DFF], g_w1l[DM*DFF];
__device__ __align__(16) __nv_bfloat16 g_w2h[DFF*DM], g_w2l[DFF*DM];

// ================= helpers =================
__device__ __forceinline__ uint32_t smem_u32(const void* p) {
    uint32_t a;
    asm("{ .reg .u64 t; cvta.to.shared.u64 t, %1; cvt.u32.u64 %0, t; }" : "=r"(a) : "l"(p));
    return a;
}
#define CP16(saddr, gptr) asm volatile( \
    "cp.async.cg.shared.global [%0], [%1], 16;" :: "r"((uint32_t)(saddr)), "l"(gptr))
#define CP_COMMIT() asm volatile("cp.async.commit_group;" ::: "memory")
#define CP_WAIT0()  asm volatile("cp.async.wait_group 0;" ::: "memory")
#define CP_WAIT1()  asm volatile("cp.async.wait_group 1;" ::: "memory")
#define CP_WAIT2()  asm volatile("cp.async.wait_group 2;" ::: "memory")

#define LDSM_X4(r, a) \
    asm volatile("ldmatrix.sync.aligned.m8n8.x4.shared.b16 {%0,%1,%2,%3}, [%4];" \
        : "=r"((r)[0]), "=r"((r)[1]), "=r"((r)[2]), "=r"((r)[3]) : "r"((uint32_t)(a)))
#define LDSM_X4T(r, a) \
    asm volatile("ldmatrix.sync.aligned.m8n8.x4.trans.shared.b16 {%0,%1,%2,%3}, [%4];" \
        : "=r"((r)[0]), "=r"((r)[1]), "=r"((r)[2]), "=r"((r)[3]) : "r"((uint32_t)(a)))

#define MMA_BF16(d, a, b) \
    asm volatile("mma.sync.aligned.m16n8k16.row.col.f32.bf16.bf16.f32 " \
        "{%0,%1,%2,%3}, {%4,%5,%6,%7}, {%8,%9}, {%0,%1,%2,%3};" \
        : "+f"((d)[0]), "+f"((d)[1]), "+f"((d)[2]), "+f"((d)[3]) \
        : "r"((a)[0]), "r"((a)[1]), "r"((a)[2]), "r"((a)[3]), "r"((b)[0]), "r"((b)[1]))

__device__ __forceinline__ void split_store4(__nv_bfloat16* H, __nv_bfloat16* L,
                                             size_t off, float4 v) {
    __nv_bfloat162 h0, h1, l0, l1;
    h0.x = __float2bfloat16_rn(v.x); h0.y = __float2bfloat16_rn(v.y);
    h1.x = __float2bfloat16_rn(v.z); h1.y = __float2bfloat16_rn(v.w);
    l0.x = __float2bfloat16_rn(v.x - __bfloat162float(h0.x));
    l0.y = __float2bfloat16_rn(v.y - __bfloat162float(h0.y));
    l1.x = __float2bfloat16_rn(v.z - __bfloat162float(h1.x));
    l1.y = __float2bfloat16_rn(v.w - __bfloat162float(h1.y));
    *(__nv_bfloat162*)(H + off)     = h0;
    *(__nv_bfloat162*)(H + off + 2) = h1;
    *(__nv_bfloat162*)(L + off)     = l0;
    *(__nv_bfloat162*)(L + off + 2) = l1;
}
__device__ __forceinline__ void split_store2(__nv_bfloat16* H, __nv_bfloat16* L,
                                             size_t off, float a, float b) {
    __nv_bfloat162 h, l;
    h.x = __float2bfloat16_rn(a); h.y = __float2bfloat16_rn(b);
    l.x = __float2bfloat16_rn(a - __bfloat162float(h.x));
    l.y = __float2bfloat16_rn(b - __bfloat162float(h.y));
    *(__nv_bfloat162*)(H + off) = h;
    *(__nv_bfloat162*)(L + off) = l;
}
__device__ __forceinline__ uint32_t pack_hi_lo(float x, float y, uint32_t* lo) {
    __nv_bfloat162 h, l;
    h.x = __float2bfloat16_rn(x); h.y = __float2bfloat16_rn(y);
    l.x = __float2bfloat16_rn(x - __bfloat162float(h.x));
    l.y = __float2bfloat16_rn(y - __bfloat162float(h.y));
    *lo = *(uint32_t*)&l;
    return *(uint32_t*)&h;
}

// ================= shared GEMM core macros (bf16x3, 3-stage cp.async) =====
#define LDE   40
#define A_SZ  (64 * LDE * 2)
#define B_SZ  (128 * LDE * 2)
#define BUF_SZ (2 * A_SZ + 2 * B_SZ)   // 30720
#define TG_SMEM (3 * BUF_SZ)           // 92160

#define TG_PREFETCH(buf, ko_)                                                    \
    {                                                                            \
        uint32_t base = sb + (buf) * BUF_SZ;                                     \
        size_t ko = (ko_);                                                       \
        CP16(base + sA, Ah + gA + ko);                                           \
        CP16(base + A_SZ + sA, Al + gA + ko);                                    \
        CP16(base + 2 * A_SZ + sB0, Bh + gB0 + ko);                              \
        CP16(base + 2 * A_SZ + sB1, Bh + gB1 + ko);                              \
        CP16(base + 2 * A_SZ + B_SZ + sB0, Bl + gB0 + ko);                       \
        CP16(base + 2 * A_SZ + B_SZ + sB1, Bl + gB1 + ko);                       \
        CP_COMMIT();                                                             \
    }

#define TG_MAINLOOP(Kvar)                                                        \
    const int nk = (Kvar) >> 5;                                                  \
    TG_PREFETCH(0, 0)                                                            \
    if (nk > 1) TG_PREFETCH(1, 32)                                               \
    for (int i = 0; i < nk; i++) {                                               \
        if (i + 2 < nk) {                                                        \
            TG_PREFETCH((i + 2) % 3, (size_t)(i + 2) * 32)                       \
            CP_WAIT2();                                                          \
        } else if (i + 1 < nk) {                                                 \
            CP_WAIT1();                                                          \
        } else {                                                                 \
            CP_WAIT0();                                                          \
        }                                                                        \
        __syncthreads();                                                         \
        uint32_t base   = sb + (i % 3) * BUF_SZ;                                 \
        uint32_t aBase  = base;                                                  \
        uint32_t alBase = base + A_SZ;                                           \
        uint32_t bBase  = base + 2 * A_SZ;                                       \
        uint32_t blBase = base + 2 * A_SZ + B_SZ;                                \
        _Pragma("unroll")                                                        \
        for (int ks = 0; ks < 32; ks += 16) {                                    \
            uint32_t ah[2][4], al[2][4], bh[2][4], bl[2][4];                     \
            uint32_t aoff = (wrow * 32 + (lane & 15)) * (LDE * 2)                \
                          + (ks + ((lane >> 4) << 3)) * 2;                       \
            _Pragma("unroll")                                                    \
            for (int mf = 0; mf < 2; mf++) {                                     \
                LDSM_X4(ah[mf], aBase + aoff + mf * 16 * (LDE * 2));             \
                LDSM_X4(al[mf], alBase + aoff + mf * 16 * (LDE * 2));            \
            }                                                                    \
            uint32_t boff = (wcol * 32 + (lane & 7) + ((lane >> 4) << 3)) * (LDE * 2) \
                          + (ks + (((lane >> 3) & 1) << 3)) * 2;                 \
            _Pragma("unroll")                                                    \
            for (int bg = 0; bg < 2; bg++) {                                     \
                LDSM_X4(bh[bg], bBase + boff + bg * 16 * (LDE * 2));             \
                LDSM_X4(bl[bg], blBase + boff + bg * 16 * (LDE * 2));            \
            }                                                                    \
            _Pragma("unroll")                                                    \
            for (int mf = 0; mf < 2; mf++)                                       \
                _Pragma("unroll")                                                \
                for (int nf = 0; nf < 4; nf++)                                   \
                    MMA_BF16(acc[mf][nf], ah[mf], &bh[nf >> 1][(nf & 1) * 2]);   \
            _Pragma("unroll")                                                    \
            for (int mf = 0; mf < 2; mf++)                                       \
                _Pragma("unroll")                                                \
                for (int nf = 0; nf < 4; nf++)                                   \
                    MMA_BF16(acc[mf][nf], ah[mf], &bl[nf >> 1][(nf & 1) * 2]);   \
            _Pragma("unroll")                                                    \
            for (int mf = 0; mf < 2; mf++)                                       \
                _Pragma("unroll")                                                \
                for (int nf = 0; nf < 4; nf++)                                   \
                    MMA_BF16(acc[mf][nf], al[mf], &bh[nf >> 1][(nf & 1) * 2]);   \
        }                                                                        \
        __syncthreads();                                                         \
    }

// ================= generic tensor-core GEMM ======================
template <int EPI>
__global__ __launch_bounds__(256, 2)
void tgemm(const __nv_bfloat16* __restrict__ Ah, const __nv_bfloat16* __restrict__ Al,
           const __nv_bfloat16* __restrict__ Bh, const __nv_bfloat16* __restrict__ Bl,
           const float* __restrict__ bias, const float* __restrict__ resid,
           float* __restrict__ outF, __nv_bfloat16* __restrict__ outH,
           __nv_bfloat16* __restrict__ outL, int M, int N, int K) {
    extern __shared__ __align__(16) char smem[];
    const uint32_t sb = smem_u32(smem);
    const int tid = threadIdx.x, wid = tid >> 5, lane = tid & 31;
    const int bx = blockIdx.x, by = blockIdx.y;
    const int wrow = wid >> 2, wcol = wid & 3;

    const int arow = tid >> 2, acg = tid & 3;
    const size_t gA  = (size_t)(by * 64 + arow) * K + acg * 8;
    const size_t gB0 = (size_t)(bx * 128 + arow) * K + acg * 8;
    const size_t gB1 = (size_t)(bx * 128 + 64 + arow) * K + acg * 8;
    const uint32_t sA  = arow * (LDE * 2) + acg * 16;
    const uint32_t sB0 = arow * (LDE * 2) + acg * 16;
    const uint32_t sB1 = (64 + arow) * (LDE * 2) + acg * 16;

    float acc[2][4][4];
#pragma unroll
    for (int i = 0; i < 2; i++)
#pragma unroll
        for (int j = 0; j < 4; j++)
#pragma unroll
            for (int t = 0; t < 4; t++) acc[i][j][t] = 0.0f;

    TG_MAINLOOP(K)

    int r0 = by * 64 + wrow * 32 + (lane >> 2);
    int c0 = bx * 128 + wcol * 32 + (lane & 3) * 2;
#pragma unroll
    for (int mf = 0; mf < 2; mf++) {
#pragma unroll
        for (int nf = 0; nf < 4; nf++) {
            int c = c0 + nf * 8;
            float bx0 = bias[c], bx1 = bias[c + 1];
#pragma unroll
            for (int hrow = 0; hrow < 2; hrow++) {
                int r = r0 + mf * 16 + hrow * 8;
                float v0 = acc[mf][nf][hrow * 2 + 0] + bx0;
                float v1 = acc[mf][nf][hrow * 2 + 1] + bx1;
                size_t off = (size_t)r * N + c;
                if (EPI == 2) {
                    float2 rv = *(const float2*)(resid + off);
                    v0 += rv.x; v1 += rv.y;
                }
                if (EPI == 1) {
                    v0 = fmaxf(v0, 0.f); v1 = fmaxf(v1, 0.f);
                    split_store2(outH, outL, off, v0, v1);
                } else {
                    *(float2*)(outF + off) = make_float2(v0, v1);
                }
            }
        }
    }
}

// ================= multi-part GEMM =================
template <int NPARTS>
__global__ __launch_bounds__(256, 2)
void tgemm_mp(const __nv_bfloat16* __restrict__ Ah, const __nv_bfloat16* __restrict__ Al,
              const __nv_bfloat16* __restrict__ Bh, const __nv_bfloat16* __restrict__ Bl,
              const float* __restrict__ b0, const float* __restrict__ b1,
              const float* __restrict__ b2,
              float* __restrict__ f0, __nv_bfloat16* __restrict__ h0, __nv_bfloat16* __restrict__ l0,
              float* __restrict__ f1, __nv_bfloat16* __restrict__ h1, __nv_bfloat16* __restrict__ l1,
              float* __restrict__ f2, __nv_bfloat16* __restrict__ h2, __nv_bfloat16* __restrict__ l2,
              int K) {
    extern __shared__ __align__(16) char smem[];
    const uint32_t sb = smem_u32(smem);
    const int tid = threadIdx.x, wid = tid >> 5, lane = tid & 31;
    const int bx = blockIdx.x, by = blockIdx.y;
    const int wrow = wid >> 2, wcol = wid & 3;

    const int arow = tid >> 2, acg = tid & 3;
    const size_t gA  = (size_t)(by * 64 + arow) * K + acg * 8;
    const size_t gB0 = (size_t)(bx * 128 + arow) * K + acg * 8;
    const size_t gB1 = (size_t)(bx * 128 + 64 + arow) * K + acg * 8;
    const uint32_t sA  = arow * (LDE * 2) + acg * 16;
    const uint32_t sB0 = arow * (LDE * 2) + acg * 16;
    const uint32_t sB1 = (64 + arow) * (LDE * 2) + acg * 16;

    float acc[2][4][4];
#pragma unroll
    for (int i = 0; i < 2; i++)
#pragma unroll
        for (int j = 0; j < 4; j++)
#pragma unroll
            for (int t = 0; t < 4; t++) acc[i][j][t] = 0.0f;

    TG_MAINLOOP(K)

    const int which = bx >> 2;
    const float* bs = (which == 0) ? b0 : (which == 1) ? b1 : b2;
    float* oF = (which == 0) ? f0 : (which == 1) ? f1 : f2;
    __nv_bfloat16* oH = (which == 0) ? h0 : (which == 1) ? h1 : h2;
    __nv_bfloat16* oL = (which == 0) ? l0 : (which == 1) ? l1 : l2;
    const bool wantF = (oF != nullptr);

    int r0 = by * 64 + wrow * 32 + (lane >> 2);
    int c0 = (bx & 3) * 128 + wcol * 32 + (lane & 3) * 2;
#pragma unroll
    for (int mf = 0; mf < 2; mf++) {
#pragma unroll
        for (int nf = 0; nf < 4; nf++) {
            int c = c0 + nf * 8;
            float bx0 = bs[c], bx1 = bs[c + 1];
#pragma unroll
            for (int hrow = 0; hrow < 2; hrow++) {
                int r = r0 + mf * 16 + hrow * 8;
                float v0 = acc[mf][nf][hrow * 2 + 0] + bx0;
                float v1 = acc[mf][nf][hrow * 2 + 1] + bx1;
                size_t off = (size_t)r * DM + c;
                if (wantF) *(float2*)(oF + off) = make_float2(v0, v1);
                split_store2(oH, oL, off, v0, v1);
            }
        }
    }
}

// ================= fused flash attention, 8 warps, key-half split ============
#define FA_LDE  144
#define FA_Q    (64 * FA_LDE)
#define FA_KV   (128 * FA_LDE)
#define FA_BUF  (4 * FA_KV)
#define FA_SMEM (2 * FA_Q + 2 * FA_BUF)

__global__ __launch_bounds__(256)
void attn_fused(const __nv_bfloat16* __restrict__ Qh, const __nv_bfloat16* __restrict__ Ql,
                const __nv_bfloat16* __restrict__ Kh, const __nv_bfloat16* __restrict__ Kl,
                const __nv_bfloat16* __restrict__ Vh, const __nv_bfloat16* __restrict__ Vl,
                const int* __restrict__ topidx, float* __restrict__ Ctx) {
    int bh = blockIdx.x, qt = blockIdx.y;
    int b = bh >> 3, h = bh & 7;
    extern __shared__ __align__(16) char smem[];
    const uint32_t sb = smem_u32(smem);
    const uint32_t qH = sb, qL = sb + FA_Q, kvBase = sb + 2 * FA_Q;
    int tid = threadIdx.x, wid = tid >> 5, lane = tid & 31;
    const int wq = wid & 3;
    const int wk = wid >> 2;
    const int kb0 = wk * 64;

    const int lr = tid >> 3, lg = tid & 7;
#pragma unroll
    for (int p = 0; p < 2; p++) {
        int idx = tid + p * 256;
        int r = idx >> 3, g = idx & 7;
        int qi = qt * 64 + r; if (qi >= UTOP) qi = UTOP - 1;
        int qrow = topidx[bh * UTOP + qi];
        size_t go = (size_t)(b * LSEQ + qrow) * DM + h * HD + g * 8;
        CP16(qH + r * FA_LDE + g * 16, Qh + go);
        CP16(qL + r * FA_LDE + g * 16, Ql + go);
    }
#pragma unroll
    for (int p = 0; p < 4; p++) {
        int r = lr + p * 32;
        size_t go = (size_t)(b * LSEQ + r) * DM + h * HD + lg * 8;
        uint32_t so = r * FA_LDE + lg * 16;
        CP16(kvBase + so, Kh + go);
        CP16(kvBase + FA_KV + so, Kl + go);
        CP16(kvBase + 2 * FA_KV + so, Vh + go);
        CP16(kvBase + 3 * FA_KV + so, Vl + go);
    }
    CP_COMMIT();

    uint32_t ah[4][4], al[4][4];
    float acco[8][4];
#pragma unroll
    for (int i = 0; i < 8; i++)
#pragma unroll
        for (int t = 0; t < 4; t++) acco[i][t] = 0.0f;
    float mrun[2] = {-1e30f, -1e30f};
    float lrun[2] = {0.0f, 0.0f};

    const int NCH = LSEQ / 128;
    for (int c = 0; c < NCH; c++) {
        if (c + 1 < NCH) {
            uint32_t base = kvBase + ((c + 1) & 1) * FA_BUF;
#pragma unroll
            for (int p = 0; p < 4; p++) {
                int r = lr + p * 32;
                size_t go = (size_t)(b * LSEQ + (c + 1) * 128 + r) * DM + h * HD + lg * 8;
                uint32_t so = r * FA_LDE + lg * 16;
                CP16(base + so, Kh + go);
                CP16(base + FA_KV + so, Kl + go);
                CP16(base + 2 * FA_KV + so, Vh + go);
                CP16(base + 3 * FA_KV + so, Vl + go);
            }
            CP_COMMIT();
            CP_WAIT1();
        } else {
            CP_WAIT0();
        }
        __syncthreads();

        if (c == 0) {
#pragma unroll
            for (int ks = 0; ks < 4; ks++) {
                uint32_t aoff = (wq * 16 + (lane & 15)) * FA_LDE
                              + (ks * 16 + ((lane >> 4) << 3)) * 2;
                LDSM_X4(ah[ks], qH + aoff);
                LDSM_X4(al[ks], qL + aoff);
            }
        }

        uint32_t kb  = kvBase + (c & 1) * FA_BUF;
        uint32_t klb = kb + FA_KV;
        uint32_t vb  = kb + 2 * FA_KV;
        uint32_t vlb = kb + 3 * FA_KV;

        float accs[8][4];
#pragma unroll
        for (int i = 0; i < 8; i++)
#pragma unroll
            for (int t = 0; t < 4; t++) accs[i][t] = 0.0f;

#pragma unroll
        for (int ks = 0; ks < 4; ks++) {
#pragma unroll
            for (int bg = 0; bg < 4; bg++) {
                uint32_t b4h[4], b4l[4];
                uint32_t boff = (kb0 + bg * 16 + (lane & 7) + ((lane >> 4) << 3)) * FA_LDE
                              + (ks * 16 + (((lane >> 3) & 1) << 3)) * 2;
                LDSM_X4(b4h, kb + boff);
                LDSM_X4(b4l, klb + boff);
                MMA_BF16(accs[2 * bg],     ah[ks], &b4h[0]);
                MMA_BF16(accs[2 * bg + 1], ah[ks], &b4h[2]);
                MMA_BF16(accs[2 * bg],     ah[ks], &b4l[0]);
                MMA_BF16(accs[2 * bg + 1], ah[ks], &b4l[2]);
                MMA_BF16(accs[2 * bg],     al[ks], &b4h[0]);
                MMA_BF16(accs[2 * bg + 1], al[ks], &b4h[2]);
            }
        }

        float alpha[2];
#pragma unroll
        for (int rg = 0; rg < 2; rg++) {
            float mx = -1e30f;
#pragma unroll
            for (int nf = 0; nf < 8; nf++)
                mx = fmaxf(mx, fmaxf(accs[nf][rg * 2], accs[nf][rg * 2 + 1]));
            mx *= 0.125f;
            mx = fmaxf(mx, __shfl_xor_sync(0xffffffffu, mx, 1));
            mx = fmaxf(mx, __shfl_xor_sync(0xffffffffu, mx, 2));
            float mnew = fmaxf(mrun[rg], mx);
            alpha[rg] = __expf(mrun[rg] - mnew);
            mrun[rg] = mnew;
        }
#pragma unroll
        for (int nf = 0; nf < 8; nf++) {
            acco[nf][0] *= alpha[0]; acco[nf][1] *= alpha[0];
            acco[nf][2] *= alpha[1]; acco[nf][3] *= alpha[1];
        }
        float rs0 = 0.0f, rs1 = 0.0f;
#pragma unroll
        for (int nf = 0; nf < 8; nf++) {
            accs[nf][0] = __expf(accs[nf][0] * 0.125f - mrun[0]);
            accs[nf][1] = __expf(accs[nf][1] * 0.125f - mrun[0]);
            accs[nf][2] = __expf(accs[nf][2] * 0.125f - mrun[1]);
            accs[nf][3] = __expf(accs[nf][3] * 0.125f - mrun[1]);
            rs0 += accs[nf][0] + accs[nf][1];
            rs1 += accs[nf][2] + accs[nf][3];
        }
        rs0 += __shfl_xor_sync(0xffffffffu, rs0, 1);
        rs0 += __shfl_xor_sync(0xffffffffu, rs0, 2);
        rs1 += __shfl_xor_sync(0xffffffffu, rs1, 1);
        rs1 += __shfl_xor_sync(0xffffffffu, rs1, 2);
        lrun[0] = lrun[0] * alpha[0] + rs0;
        lrun[1] = lrun[1] * alpha[1] + rs1;

#pragma unroll
        for (int ks2 = 0; ks2 < 4; ks2++) {
            uint32_t pa_h[4], pa_l[4];
            pa_h[0] = pack_hi_lo(accs[2 * ks2][0],     accs[2 * ks2][1],     &pa_l[0]);
            pa_h[1] = pack_hi_lo(accs[2 * ks2][2],     accs[2 * ks2][3],     &pa_l[1]);
            pa_h[2] = pack_hi_lo(accs[2 * ks2 + 1][0], accs[2 * ks2 + 1][1], &pa_l[2]);
            pa_h[3] = pack_hi_lo(accs[2 * ks2 + 1][2], accs[2 * ks2 + 1][3], &pa_l[3]);
#pragma unroll
            for (int dg = 0; dg < 4; dg++) {
                uint32_t bth[4], btl[4];
                uint32_t boff = (kb0 + ks2 * 16 + (lane & 7) + (((lane >> 3) & 1) << 3)) * FA_LDE
                              + (dg * 16 + ((lane >> 4) << 3)) * 2;
                LDSM_X4T(bth, vb + boff);
                LDSM_X4T(btl, vlb + boff);
                MMA_BF16(acco[2 * dg],     pa_h, &bth[0]);
                MMA_BF16(acco[2 * dg + 1], pa_h, &bth[2]);
                MMA_BF16(acco[2 * dg],     pa_h, &btl[0]);
                MMA_BF16(acco[2 * dg + 1], pa_h, &btl[2]);
                MMA_BF16(acco[2 * dg],     pa_l, &bth[0]);
                MMA_BF16(acco[2 * dg + 1], pa_l, &bth[2]);
            }
        }
        __syncthreads();
    }

    float* msh = (float*)(smem + 2 * FA_Q);
    if (wk == 1) {
        float* p = msh + ((size_t)(wq * 32 + lane)) * 36;
#pragma unroll
        for (int nf = 0; nf < 8; nf++) {
            p[nf * 4 + 0] = acco[nf][0]; p[nf * 4 + 1] = acco[nf][1];
            p[nf * 4 + 2] = acco[nf][2]; p[nf * 4 + 3] = acco[nf][3];
        }
        p[32] = mrun[0]; p[33] = mrun[1]; p[34] = lrun[0]; p[35] = lrun[1];
    }
    __syncthreads();
    if (wk == 0) {
        float* p = msh + ((size_t)(wq * 32 + lane)) * 36;
        float m1_0 = p[32], m1_1 = p[33], l1_0 = p[34], l1_1 = p[35];
        float mn0 = fmaxf(mrun[0], m1_0), mn1 = fmaxf(mrun[1], m1_1);
        float f00 = __expf(mrun[0] - mn0), f01 = __expf(m1_0 - mn0);
        float f10 = __expf(mrun[1] - mn1), f11 = __expf(m1_1 - mn1);
        float lt0 = lrun[0] * f00 + l1_0 * f01;
        float lt1 = lrun[1] * f10 + l1_1 * f11;
        float inv0 = 1.0f / lt0, inv1 = 1.0f / lt1;

        int r = wq * 16 + (lane >> 2);
        int c = (lane & 3) * 2;
        int qi0 = qt * 64 + r, qi1 = qt * 64 + r + 8;
#pragma unroll
        for (int nf = 0; nf < 8; nf++) {
            float o0 = (acco[nf][0] * f00 + p[nf * 4 + 0] * f01) * inv0;
            float o1 = (acco[nf][1] * f00 + p[nf * 4 + 1] * f01) * inv0;
            float o2 = (acco[nf][2] * f10 + p[nf * 4 + 2] * f11) * inv1;
            float o3 = (acco[nf][3] * f10 + p[nf * 4 + 3] * f11) * inv1;
            if (qi0 < UTOP)
                *(float2*)(Ctx + (size_t)(bh * UTOP + qi0) * HD + nf * 8 + c) =
                    make_float2(o0, o1);
            if (qi1 < UTOP)
                *(float2*)(Ctx + (size_t)(bh * UTOP + qi1) * HD + nf * 8 + c) =
                    make_float2(o2, o3);
        }
    }
}

// ================= weight transpose + bf16 split =================
__global__ void wconv_kernel(const float* __restrict__ W, __nv_bfloat16* __restrict__ Th,
                             __nv_bfloat16* __restrict__ Tl, int K, int N) {
    __shared__ float t[32][33];
    int k0 = blockIdx.y * 32, n0 = blockIdx.x * 32;
    int tx = threadIdx.x, ty = threadIdx.y;
#pragma unroll
    for (int i = 0; i < 4; i++)
        t[ty + i * 8][tx] = W[(size_t)(k0 + ty + i * 8) * N + n0 + tx];
    __syncthreads();
#pragma unroll
    for (int i = 0; i < 4; i++) {
        float v = t[tx][ty + i * 8];
        size_t o = (size_t)(n0 + ty + i * 8) * K + k0 + tx;
        __nv_bfloat16 h = __float2bfloat16_rn(v);
        Th[o] = h;
        Tl[o] = __float2bfloat16_rn(v - __bfloat162float(h));
    }
}

__global__ void wconv4_kernel(const float* __restrict__ W0, const float* __restrict__ W1,
                              const float* __restrict__ W2, const float* __restrict__ W3,
                              __nv_bfloat16* __restrict__ T0h, __nv_bfloat16* __restrict__ T0l,
                              __nv_bfloat16* __restrict__ T1h, __nv_bfloat16* __restrict__ T1l,
                              __nv_bfloat16* __restrict__ T2h, __nv_bfloat16* __restrict__ T2l,
                              __nv_bfloat16* __restrict__ T3h, __nv_bfloat16* __restrict__ T3l) {
    __shared__ float t[32][33];
    int z = blockIdx.z;
    const float* W = (z == 0) ? W0 : (z == 1) ? W1 : (z == 2) ? W2 : W3;
    __nv_bfloat16* Th = (z == 0) ? T0h : (z == 1) ? T1h : (z == 2) ? T2h : T3h;
    __nv_bfloat16* Tl = (z == 0) ? T0l : (z == 1) ? T1l : (z == 2) ? T2l : T3l;
    int k0 = blockIdx.y * 32, n0 = blockIdx.x * 32;
    int tx = threadIdx.x, ty = threadIdx.y;
#pragma unroll
    for (int i = 0; i < 4; i++)
        t[ty + i * 8][tx] = W[(size_t)(k0 + ty + i * 8) * DM + n0 + tx];
    __syncthreads();
#pragma unroll
    for (int i = 0; i < 4; i++) {
        float v = t[tx][ty + i * 8];
        size_t o = (size_t)(n0 + ty + i * 8) * DM + k0 + tx;
        __nv_bfloat16 h = __float2bfloat16_rn(v);
        Th[o] = h;
        Tl[o] = __float2bfloat16_rn(v - __bfloat162float(h));
    }
}

// ================= LayerNorm, warp-per-row =================
__global__ __launch_bounds__(256)
void ln_kernel(const float* __restrict__ X, const float* __restrict__ gam,
               const float* __restrict__ bet, __nv_bfloat16* __restrict__ Yh,
               __nv_bfloat16* __restrict__ Yl) {
    int warp = threadIdx.x >> 5, lane = threadIdx.x & 31;
    int row = blockIdx.x * 8 + warp;
    const float* xr = X + (size_t)row * DM;
    float4 v[4];
    float s = 0.0f, q = 0.0f;
#pragma unroll
    for (int i = 0; i < 4; i++) {
        v[i] = *(const float4*)(xr + (lane + i * 32) * 4);
        s += v[i].x + v[i].y + v[i].z + v[i].w;
        q += v[i].x * v[i].x + v[i].y * v[i].y + v[i].z * v[i].z + v[i].w * v[i].w;
    }
#pragma unroll
    for (int o = 16; o > 0; o >>= 1) {
        s += __shfl_xor_sync(0xffffffffu, s, o);
        q += __shfl_xor_sync(0xffffffffu, q, o);
    }
    float mean = s * (1.0f / DM);
    float var  = q * (1.0f / DM) - mean * mean;
    float rs   = rsqrtf(var + 1e-5f);
#pragma unroll
    for (int i = 0; i < 4; i++) {
        int c = (lane + i * 32) * 4;
        float4 gg = *(const float4*)(gam + c);
        float4 bb = *(const float4*)(bet + c);
        float4 o;
        o.x = (v[i].x - mean) * rs * gg.x + bb.x;
        o.y = (v[i].y - mean) * rs * gg.y + bb.y;
        o.z = (v[i].z - mean) * rs * gg.z + bb.z;
        o.w = (v[i].w - mean) * rs * gg.w + bb.w;
        split_store4(Yh, Yl, (size_t)row * DM + c, o);
    }
}

// ================= topk stage 1: partial kmean over 32 rows/block ===========
__global__ __launch_bounds__(256)
void kmean_part(const float* __restrict__ Kp, float* __restrict__ kpart) {
    int bh = blockIdx.x, ch = blockIdx.y;
    int b = bh >> 3, h = bh & 7;
    __shared__ float warpacc[8][64];
    int warp = threadIdx.x >> 5, lane = threadIdx.x & 31;
    float2 acc = make_float2(0.0f, 0.0f);
    int base = ch * (LSEQ / TKCH);
#pragma unroll
    for (int i = 0; i < LSEQ / TKCH / 8; i++) {
        int l = base + warp + i * 8;
        float2 kv = *(const float2*)(Kp + (size_t)(b * LSEQ + l) * DM + h * HD + lane * 2);
        float ssq = kv.x * kv.x + kv.y * kv.y;
#pragma unroll
        for (int o = 16; o > 0; o >>= 1) ssq += __shfl_xor_sync(0xffffffffu, ssq, o);
        float rn = 1.0f / sqrtf(ssq);
        acc.x += kv.x * rn;
        acc.y += kv.y * rn;
    }
    warpacc[warp][lane * 2]     = acc.x;
    warpacc[warp][lane * 2 + 1] = acc.y;
    __syncthreads();
    if (threadIdx.x < 64) {
        float s = 0.0f;
#pragma unroll
        for (int w = 0; w < 8; w++) s += warpacc[w][threadIdx.x];
        kpart[(bh * TKCH + ch) * 64 + threadIdx.x] = s;
    }
}

// ================= topk stage 2: score keys for 32 rows/block ===============
__global__ __launch_bounds__(256)
void score_kernel(const float* __restrict__ Q, const float* __restrict__ kpart,
                  uint32_t* __restrict__ keys) {
    int bh = blockIdx.x, ch = blockIdx.y;
    int b = bh >> 3, h = bh & 7;
    __shared__ float kmean[64];
    if (threadIdx.x < 64) {
        float s = 0.0f;
#pragma unroll
        for (int c = 0; c < TKCH; c++) s += kpart[(bh * TKCH + c) * 64 + threadIdx.x];
        kmean[threadIdx.x] = s * (1.0f / LSEQ);
    }
    __syncthreads();
    int warp = threadIdx.x >> 5, lane = threadIdx.x & 31;
    int base = ch * (LSEQ / TKCH);
    float km0 = kmean[lane * 2], km1 = kmean[lane * 2 + 1];
#pragma unroll
    for (int i = 0; i < LSEQ / TKCH / 8; i++) {
        int l = base + warp + i * 8;
        float2 qv = *(const float2*)(Q + (size_t)(b * LSEQ + l) * DM + h * HD + lane * 2);
        float ssq = qv.x * qv.x + qv.y * qv.y;
        float dt  = qv.x * km0 + qv.y * km1;
#pragma unroll
        for (int o = 16; o > 0; o >>= 1) {
            ssq += __shfl_xor_sync(0xffffffffu, ssq, o);
            dt  += __shfl_xor_sync(0xffffffffu, dt, o);
        }
        if (lane == 0) {
            float scv = dt / sqrtf(ssq);
            unsigned u = __float_as_uint(scv);
            u = (u & 0x80000000u) ? ~u : (u | 0x80000000u);
            keys[bh * LSEQ + l] = u;
        }
    }
}

// ================= topk stage 3: radix select + ordered compaction ===========
__global__ __launch_bounds__(1024)
void select_kernel(const uint32_t* __restrict__ keys, int* __restrict__ topidx) {
    int bh = blockIdx.x;
    __shared__ uint32_t ukey[LSEQ];
    __shared__ int hist[2048];
    __shared__ int s_bin, s_rank, s_above;
    __shared__ int wsumG[32], woffG[32], wsumE[32], woffE[32];
    __shared__ int s_gbase, s_ebase, s_gtot, s_etot;
    int tid = threadIdx.x, warp = tid >> 5, lane = tid & 31;

    for (int i = tid; i < LSEQ; i += 1024) ukey[i] = keys[bh * LSEQ + i];

    int rank = UTOP;
    uint32_t pref = 0;
    int prevshift = 0;
    int cntG = 0;
    const int shifts[3] = {21, 10, 0};
    const int widths[3] = {11, 11, 10};
#pragma unroll
    for (int lev = 0; lev < 3; lev++) {
        int nb = 1 << widths[lev];
        __syncthreads();
        for (int i = tid; i < nb; i += 1024) hist[i] = 0;
        __syncthreads();
        for (int i = tid; i < LSEQ; i += 1024) {
            uint32_t u = ukey[i];
            bool m = (lev == 0) || ((u >> prevshift) == pref);
            if (m) atomicAdd(&hist[(u >> shifts[lev]) & (nb - 1)], 1);
        }
        __syncthreads();
        if (warp == 0) {
            int running = 0;
            for (int cbase = nb - 32; cbase >= 0; cbase -= 32) {
                int bin = cbase + (31 - lane);
                int v = hist[bin];
                int cum = v;
#pragma unroll
                for (int o = 1; o < 32; o <<= 1) {
                    int t = __shfl_up_sync(0xffffffffu, cum, o);
                    if (lane >= o) cum += t;
                }
                int tot = __shfl_sync(0xffffffffu, cum, 31);
                unsigned ball = __ballot_sync(0xffffffffu, running + cum >= rank);
                if (ball) {
                    int fl = __ffs(ball) - 1;
                    if (lane == fl) {
                        s_bin   = bin;
                        s_above = running + cum - v;
                        s_rank  = rank - (running + cum - v);
                    }
                    break;
                }
                running += tot;
            }
        }
        __syncthreads();
        cntG += s_above;
        rank  = s_rank;
        pref  = (lev == 0) ? (uint32_t)s_bin
                           : ((pref << widths[lev]) | (uint32_t)s_bin);
        prevshift = shifts[lev];
        __syncthreads();
    }
    const uint32_t T = pref;
    const int needEq = rank;

    if (tid == 0) { s_gbase = 0; s_ebase = 0; }
    __syncthreads();
    unsigned lmask = (1u << lane) - 1;
#pragma unroll
    for (int ph = 0; ph < 2; ph++) {
        int i = ph * 1024 + tid;
        uint32_t u = ukey[i];
        bool pg = (u > T);
        bool pe = (u == T);
        unsigned bg = __ballot_sync(0xffffffffu, pg);
        unsigned be = __ballot_sync(0xffffffffu, pe);
        if (lane == 0) { wsumG[warp] = __popc(bg); wsumE[warp] = __popc(be); }
        __syncthreads();
        if (warp == 0) {
            int vg = wsumG[lane], ve = wsumE[lane];
            int cg = vg, ce = ve;
#pragma unroll
            for (int o = 1; o < 32; o <<= 1) {
                int tg = __shfl_up_sync(0xffffffffu, cg, o);
                int te = __shfl_up_sync(0xffffffffu, ce, o);
                if (lane >= o) { cg += tg; ce += te; }
            }
            woffG[lane] = cg - vg;
            woffE[lane] = ce - ve;
            if (lane == 31) { s_gtot = cg; s_etot = ce; }
        }
        __syncthreads();
        if (pg) {
            int pos = s_gbase + woffG[warp] + __popc(bg & lmask);
            topidx[bh * UTOP + pos] = i;
        }
        if (pe) {
            int ep = s_ebase + woffE[warp] + __popc(be & lmask);
            if (ep < needEq) topidx[bh * UTOP + cntG + ep] = i;
        }
        __syncthreads();
        if (tid == 0) { s_gbase += s_gtot; s_ebase += s_etot; }
        __syncthreads();
    }
}

// ================= zero bf16 pair =================
__global__ void zero2_kernel(__nv_bfloat16* __restrict__ a, __nv_bfloat16* __restrict__ b) {
    size_t i = (size_t)(blockIdx.x * 256 + threadIdx.x) * 8;
    uint4 z = make_uint4(0, 0, 0, 0);
    *(uint4*)(a + i) = z;
    *(uint4*)(b + i) = z;
}

// ================= scatter ctx rows -> bf16-pair full context =================
__global__ void scatter_kernel(const float* __restrict__ Ctx, const int* __restrict__ topidx,
                               __nv_bfloat16* __restrict__ CfH, __nv_bfloat16* __restrict__ CfL) {
    int bh = blockIdx.x, qt = blockIdx.y;
    int b = bh >> 3, h = bh & 7;
    int tid = threadIdx.x;
#pragma unroll
    for (int p = 0; p < 4; p++) {
        int idx = tid + p * 256;
        int r = idx / 16, c4 = (idx % 16) * 4;
        int qi = qt * 64 + r;
        if (qi < UTOP) {
            int l = topidx[bh * UTOP + qi];
            float4 v = *(const float4*)(Ctx + ((size_t)bh * UTOP + qi) * HD + c4);
            split_store4(CfH, CfL, (size_t)(b * LSEQ + l) * DM + h * HD + c4, v);
        }
    }
}

// ================= fp32 -> bf16 pair split (for enc_out) =================
__global__ void enc_split_kernel(const float* __restrict__ X,
                                 __nv_bfloat16* __restrict__ H,
                                 __nv_bfloat16* __restrict__ L) {
    size_t i = (size_t)(blockIdx.x * 256 + threadIdx.x) * 4;
    float4 v = *(const float4*)(X + i);
    split_store4(H, L, i, v);
}

// ================= launch =================
extern "C" void kernel_launch(void* const* d_in, const int* in_sizes, int n_in,
                              void* d_out, int out_size) {
    const float* x      = (const float*)d_in[0];
    const float* enc    = (const float*)d_in[1];
    const float* sa_wq  = (const float*)d_in[2];
    const float* sa_bq  = (const float*)d_in[3];
    const float* sa_wk  = (const float*)d_in[4];
    const float* sa_bk  = (const float*)d_in[5];
    const float* sa_wv  = (const float*)d_in[6];
    const float* sa_bv  = (const float*)d_in[7];
    const float* sa_wo  = (const float*)d_in[8];
    const float* sa_bo  = (const float*)d_in[9];
    const float* ca_wq  = (const float*)d_in[10];
    const float* ca_bq  = (const float*)d_in[11];
    const float* ca_wk  = (const float*)d_in[12];
    const float* ca_bk  = (const float*)d_in[13];
    const float* ca_wv  = (const float*)d_in[14];
    const float* ca_bv  = (const float*)d_in[15];
    const float* ca_wo  = (const float*)d_in[16];
    const float* ca_bo  = (const float*)d_in[17];
    const float* ff_w1  = (const float*)d_in[18];
    const float* ff_b1  = (const float*)d_in[19];
    const float* ff_w2  = (const float*)d_in[20];
    const float* ff_b2  = (const float*)d_in[21];
    const float* ln1_g  = (const float*)d_in[22];
    const float* ln1_b  = (const float*)d_in[23];
    const float* ln2_g  = (const float*)d_in[24];
    const float* ln2_b  = (const float*)d_in[25];
    const float* ln3_g  = (const float*)d_in[26];
    const float* ln3_b  = (const float*)d_in[27];
    float* out = (float*)d_out;

    float *q, *k, *ctx, *x1, *x2, *kpart;
    int* ti;
    uint32_t* keys;
    __nv_bfloat16 *xnh, *xnl, *cfh, *cfl, *hidh, *hidl;
    __nv_bfloat16 *qh, *ql, *kh, *kl, *vh, *vl;
    __nv_bfloat16 *wqkvh, *wqkvl, *woh, *wol;
    __nv_bfloat16 *cwqh, *cwql, *cwkvh, *cwkvl, *cwoh, *cwol;
    __nv_bfloat16 *w1h, *w1l, *w2h, *w2l;
    cudaGetSymbolAddress((void**)&q,   g_qb);
    cudaGetSymbolAddress((void**)&k,   g_kb);
    cudaGetSymbolAddress((void**)&ctx, g_ctx);
    cudaGetSymbolAddress((void**)&x1,  g_x1);
    cudaGetSymbolAddress((void**)&x2,  g_x2);
    cudaGetSymbolAddress((void**)&ti,  g_ti);
    cudaGetSymbolAddress((void**)&kpart, g_kpart);
    cudaGetSymbolAddress((void**)&keys,  g_keys);
    cudaGetSymbolAddress((void**)&xnh, g_xnh);
    cudaGetSymbolAddress((void**)&xnl, g_xnl);
    cudaGetSymbolAddress((void**)&cfh, g_cfh);
    cudaGetSymbolAddress((void**)&cfl, g_cfl);
    cudaGetSymbolAddress((void**)&hidh, g_hidh);
    cudaGetSymbolAddress((void**)&hidl, g_hidl);
    cudaGetSymbolAddress((void**)&qh, g_qh);
    cudaGetSymbolAddress((void**)&ql, g_ql);
    cudaGetSymbolAddress((void**)&kh, g_kh);
    cudaGetSymbolAddress((void**)&kl, g_kl);
    cudaGetSymbolAddress((void**)&vh, g_vh);
    cudaGetSymbolAddress((void**)&vl, g_vl);
    cudaGetSymbolAddress((void**)&wqkvh, g_wqkvh);
    cudaGetSymbolAddress((void**)&wqkvl, g_wqkvl);
    cudaGetSymbolAddress((void**)&woh, g_woh);
    cudaGetSymbolAddress((void**)&wol, g_wol);
    cudaGetSymbolAddress((void**)&cwqh, g_cwqh);
    cudaGetSymbolAddress((void**)&cwql, g_cwql);
    cudaGetSymbolAddress((void**)&cwkvh, g_cwkvh);
    cudaGetSymbolAddress((void**)&cwkvl, g_cwkvl);
    cudaGetSymbolAddress((void**)&cwoh, g_cwoh);
    cudaGetSymbolAddress((void**)&cwol, g_cwol);
    cudaGetSymbolAddress((void**)&w1h, g_w1h);
    cudaGetSymbolAddress((void**)&w1l, g_w1l);
    cudaGetSymbolAddress((void**)&w2h, g_w2h);
    cudaGetSymbolAddress((void**)&w2l, g_w2l);

    cudaFuncSetAttribute(tgemm<0>, cudaFuncAttributeMaxDynamicSharedMemorySize, TG_SMEM);
    cudaFuncSetAttribute(tgemm<1>, cudaFuncAttributeMaxDynamicSharedMemorySize, TG_SMEM);
    cudaFuncSetAttribute(tgemm<2>, cudaFuncAttributeMaxDynamicSharedMemorySize, TG_SMEM);
    cudaFuncSetAttribute(tgemm_mp<2>, cudaFuncAttributeMaxDynamicSharedMemorySize, TG_SMEM);
    cudaFuncSetAttribute(tgemm_mp<3>, cudaFuncAttributeMaxDynamicSharedMemorySize, TG_SMEM);
    cudaFuncSetAttribute(attn_fused, cudaFuncAttributeMaxDynamicSharedMemorySize, FA_SMEM);

    dim3 wcb(32, 8);
    dim3 wcg4(DM / 32, DM / 32, 4);
    dim3 wcg1(DFF / 32, DM / 32);
    dim3 wcg2(DM / 32, DFF / 32);
    dim3 gQKV(12, NROWS / 64);
    dim3 gKV(8, NROWS / 64);
    dim3 gQ1(4, NROWS / 64);
    dim3 gP(DM / 128, NROWS / 64);
    dim3 gF1(DFF / 128, NROWS / 64);
    dim3 gAttn(NBH, 7);
    dim3 gCtx(NBH, 7);
    dim3 gLN(NROWS / 8);
    dim3 gTK(NBH, TKCH);

    // ===== self attention (QKV GEMM placed as launch #4 for ncu slot) =====
    wconv4_kernel<<<wcg4, wcb>>>(sa_wq, sa_wk, sa_wv, sa_wo,
                                 wqkvh, wqkvl,
                                 wqkvh + DM * DM, wqkvl + DM * DM,
                                 wqkvh + 2 * DM * DM, wqkvl + 2 * DM * DM,
                                 woh, wol);
    ln_kernel<<<gLN, 256>>>(x, ln1_g, ln1_b, xnh, xnl);
    wconv_kernel<<<wcg1, wcb>>>(ff_w1, w1h, w1l, DM, DFF);
    tgemm_mp<3><<<gQKV, 256, TG_SMEM>>>(xnh, xnl, wqkvh, wqkvl,
                                        sa_bq, sa_bk, sa_bv,
                                        q, qh, ql, k, kh, kl, nullptr, vh, vl, DM);
    kmean_part<<<gTK, 256>>>(k, kpart);
    score_kernel<<<gTK, 256>>>(q, kpart, keys);
    select_kernel<<<NBH, 1024>>>(keys, ti);
    attn_fused<<<gAttn, 256, FA_SMEM>>>(qh, ql, kh, kl, vh, vl, ti, ctx);
    zero2_kernel<<<NROWS * DM / (256 * 8), 256>>>(cfh, cfl);
    scatter_kernel<<<gCtx, 256>>>(ctx, ti, cfh, cfl);
    tgemm<2><<<gP, 256, TG_SMEM>>>(cfh, cfl, woh, wol, sa_bo, x, x1, nullptr, nullptr, NROWS, DM, DM);

    // remaining weight conversions
    wconv4_kernel<<<wcg4, wcb>>>(ca_wq, ca_wk, ca_wv, ca_wo,
                                 cwqh, cwql,
                                 cwkvh, cwkvl,
                                 cwkvh + DM * DM, cwkvl + DM * DM,
                                 cwoh, cwol);
    wconv_kernel<<<wcg2, wcb>>>(ff_w2, w2h, w2l, DFF, DM);

    // ===== cross attention =====
    ln_kernel<<<gLN, 256>>>(x1, ln2_g, ln2_b, xnh, xnl);
    tgemm_mp<2><<<gQ1, 256, TG_SMEM>>>(xnh, xnl, cwqh, cwql,
                                       ca_bq, nullptr, nullptr,
                                       q, qh, ql,
                                       nullptr, nullptr, nullptr,
                                       nullptr, nullptr, nullptr, DM);
    enc_split_kernel<<<NROWS * DM / (256 * 4), 256>>>(enc, hidh, hidl);
    tgemm_mp<2><<<gKV, 256, TG_SMEM>>>(hidh, hidl, cwkvh, cwkvl,
                                       ca_bk, ca_bv, nullptr,
                                       k, kh, kl, nullptr, vh, vl,
                                       nullptr, nullptr, nullptr, DM);
    kmean_part<<<gTK, 256>>>(k, kpart);
    score_kernel<<<gTK, 256>>>(q, kpart, keys);
    select_kernel<<<NBH, 1024>>>(keys, ti);
    attn_fused<<<gAttn, 256, FA_SMEM>>>(qh, ql, kh, kl, vh, vl, ti, ctx);
    zero2_kernel<<<NROWS * DM / (256 * 8), 256>>>(cfh, cfl);
    scatter_kernel<<<gCtx, 256>>>(ctx, ti, cfh, cfl);
    tgemm<2><<<gP, 256, TG_SMEM>>>(cfh, cfl, cwoh, cwol, ca_bo, x1, x2, nullptr, nullptr, NROWS, DM, DM);

    // ===== FFN =====
    ln_kernel<<<gLN, 256>>>(x2, ln3_g, ln3_b, xnh, xnl);
    tgemm<1><<<gF1, 256, TG_SMEM>>>(xnh, xnl, w1h, w1l, ff_b1, nullptr, nullptr, hidh, hidl, NROWS, DFF, DM);
    tgemm<2><<<gP, 256, TG_SMEM>>>(hidh, hidl, w2h, w2l, ff_b2, x2, out, nullptr, nullptr, NROWS, DM, DFF);
}